// round 15
// baseline (speedup 1.0000x reference)
#include <cuda_runtime.h>
#include <cstdint>
#include <cstddef>

// Problem constants
constexpr int kL   = 2;
constexpr int kHS  = 512;
constexpr int kIN  = 512;
constexpr int kB   = 64;
constexpr int kS   = 1024;
constexpr int kM   = 2048;              // (l,g,h): m = (l*2+g)*512 + h   (g: 0=z, 1=n)
constexpr int kK   = 512;
constexpr int kN   = kS * kB;           // n = t*64 + b

// ---------------- device scratch (static allocation, allowed) ----------------
__device__ float    g_Weff[(size_t)kM * kK];          // 4 MB
__device__ float    g_Ueff[(size_t)kM * kK];          // 4 MB
__device__ float    g_bias[kM];
__device__ float    g_Gx[(size_t)kS * kM * kB];       // 512 MB: [t][m][b]
__device__ float    g_h[2][kL * kHS * kB];            // ping-pong, [l][h][b]
__device__ unsigned g_barc[2 * 32];                   // single counter/layer, 128B apart

// ---------------- packed f32x2 helpers ----------------
__device__ __forceinline__ unsigned long long pk2(float x, float y) {
    unsigned long long r;
    asm("mov.b64 %0, {%1, %2};" : "=l"(r) : "f"(x), "f"(y));
    return r;
}
__device__ __forceinline__ void fma2(unsigned long long& c, unsigned long long a, unsigned long long b) {
    asm("fma.rn.f32x2 %0, %1, %2, %0;" : "+l"(c) : "l"(a), "l"(b));
}
__device__ __forceinline__ float2 up2(unsigned long long v) {
    float lo, hi;
    asm("mov.b64 {%0, %1}, %2;" : "=f"(lo), "=f"(hi) : "l"(v));
    return make_float2(lo, hi);
}

__device__ __forceinline__ uint32_t smem_u32(const void* p) {
    uint32_t a;
    asm("{ .reg .u64 t; cvta.to.shared.u64 t, %1; cvt.u32.u64 %0, t; }" : "=r"(a) : "l"(p));
    return a;
}
__device__ __forceinline__ void mbar_init(uint32_t addr, uint32_t cnt) {
    asm volatile("mbarrier.init.shared.b64 [%0], %1;" :: "r"(addr), "r"(cnt) : "memory");
}
__device__ __forceinline__ void mbar_expect_tx(uint32_t addr, uint32_t bytes) {
    asm volatile("mbarrier.arrive.expect_tx.shared.b64 _, [%0], %1;" :: "r"(addr), "r"(bytes) : "memory");
}
__device__ __forceinline__ void mbar_wait(uint32_t addr, uint32_t phase) {
    asm volatile(
        "{\n\t.reg .pred P;\n\t"
        "W%=:\n\t"
        "mbarrier.try_wait.parity.acquire.cta.shared::cta.b64 P, [%0], %1, 0x989680;\n\t"
        "@!P bra W%=;\n\t}"
        :: "r"(addr), "r"(phase) : "memory");
}
__device__ __forceinline__ void bulk_g2s(uint32_t dst, const void* src, uint32_t bytes, uint32_t mbar) {
    asm volatile(
        "cp.async.bulk.shared::cta.global.mbarrier::complete_tx::bytes [%0], [%1], %2, [%3];"
        :: "r"(dst), "l"(src), "r"(bytes), "r"(mbar) : "memory");
}

// =====================================================================
// Prep: fold rank-1 gate scalars into effective weights, init h, bias, barriers
// =====================================================================
__global__ void prep_kernel(const float* __restrict__ h0,
                            const float* __restrict__ W1, const float* __restrict__ W2,
                            const float* __restrict__ U1, const float* __restrict__ U2,
                            const float* __restrict__ dW1, const float* __restrict__ dW2,
                            const float* __restrict__ dU1, const float* __restrict__ dU2,
                            const float* __restrict__ b1, const float* __restrict__ b2)
{
    int gsz = gridDim.x * blockDim.x;
    int gid = blockIdx.x * blockDim.x + threadIdx.x;

    for (int i = gid; i < kM * kK; i += gsz) {
        int m = i >> 9, k = i & 511;
        int l = m >> 10, g = (m >> 9) & 1, h = m & 511;
        // gate index in the 3-gate source: z=1, n=2 (r unused)
        float w1  = W1[l * 3 + g + 1],  dw1 = dW1[l * 3 + g + 1];
        float u1  = U1[l * 3 + g + 1],  du1 = dU1[l * 3 + g + 1];
        int wi = (l * kHS + h) * kIN + k;
        g_Weff[i] = w1 * W2[wi] + dw1 * dW2[wi];
        g_Ueff[i] = u1 * U2[wi] + du1 * dU2[wi];
        if (k == 0) {
            int bi = l * 3 * kHS + (g + 1) * kHS + h;
            g_bias[m] = b1[bi] + b2[bi];
        }
    }
    // h buffer [l][h][b] <- h0 (L,B,HS)
    for (int j = gid; j < kL * kHS * kB; j += gsz) {
        int l = j >> 15;
        int h = (j >> 6) & 511;
        int b = j & 63;
        g_h[0][j] = h0[(l * kB + b) * kHS + h];
    }
    if (gid < 2 * 32) g_barc[gid] = 0u;
}

// =====================================================================
// Phase A: Gx[t][m][b] = sum_k Weff[m][k] * x[b][t][k]
// 128x128x16 tiles, 256 threads, 8x8 per thread, f32x2 packed FMA
// =====================================================================
constexpr int GBM = 128, GBN = 128, GBK = 16, GPAD = 4;

__global__ void __launch_bounds__(256, 2) gemm_kernel(const float* __restrict__ x)
{
    __shared__ __align__(16) float As[GBK][GBM + GPAD];
    __shared__ __align__(16) float Bs[GBK][GBN + GPAD];

    int tid = threadIdx.x;
    int m0 = blockIdx.y * GBM;     // grid.y = 16
    int n0 = blockIdx.x * GBN;     // grid.x = 512
    int tm = tid >> 4, tn = tid & 15;

    unsigned long long c[8][4];
#pragma unroll
    for (int i = 0; i < 8; i++)
#pragma unroll
        for (int j = 0; j < 4; j++) c[i][j] = 0ull;

    for (int kt = 0; kt < kK; kt += GBK) {
#pragma unroll
        for (int it = 0; it < 2; it++) {
            int fid = tid + it * 256;
            int row = fid >> 2;
            int k4  = (fid & 3) * 4;
            float4 av = *reinterpret_cast<const float4*>(
                &g_Weff[(size_t)(m0 + row) * kK + kt + k4]);
            As[k4 + 0][row] = av.x; As[k4 + 1][row] = av.y;
            As[k4 + 2][row] = av.z; As[k4 + 3][row] = av.w;
            int n = n0 + row;
            int b = n & 63, t = n >> 6;
            float4 bv = *reinterpret_cast<const float4*>(
                &x[((size_t)b * kS + t) * kIN + kt + k4]);
            Bs[k4 + 0][row] = bv.x; Bs[k4 + 1][row] = bv.y;
            Bs[k4 + 2][row] = bv.z; Bs[k4 + 3][row] = bv.w;
        }
        __syncthreads();
#pragma unroll
        for (int kk = 0; kk < GBK; kk++) {
            float4 alo = *reinterpret_cast<const float4*>(&As[kk][tm * 8]);
            float4 ahi = *reinterpret_cast<const float4*>(&As[kk][tm * 8 + 4]);
            float a[8] = {alo.x, alo.y, alo.z, alo.w, ahi.x, ahi.y, ahi.z, ahi.w};
            ulonglong2 b01 = *reinterpret_cast<const ulonglong2*>(&Bs[kk][tn * 8]);
            ulonglong2 b23 = *reinterpret_cast<const ulonglong2*>(&Bs[kk][tn * 8 + 4]);
            unsigned long long bq[4] = {b01.x, b01.y, b23.x, b23.y};
#pragma unroll
            for (int i = 0; i < 8; i++) {
                unsigned long long ad = pk2(a[i], a[i]);
#pragma unroll
                for (int j = 0; j < 4; j++) fma2(c[i][j], ad, bq[j]);
            }
        }
        __syncthreads();
    }

    // store: the 8 n-values per thread stay within one t (8 | 64)
    int nbase = n0 + tn * 8;
    int b0 = nbase & 63;
    int tt = nbase >> 6;
#pragma unroll
    for (int i = 0; i < 8; i++) {
        int m = m0 + tm * 8 + i;
        float* dst = &g_Gx[((size_t)tt * kM + m) * kB + b0];
        float2 p0 = up2(c[i][0]), p1 = up2(c[i][1]);
        float2 p2 = up2(c[i][2]), p3 = up2(c[i][3]);
        *reinterpret_cast<float4*>(dst)     = make_float4(p0.x, p0.y, p1.x, p1.y);
        *reinterpret_cast<float4*>(dst + 4) = make_float4(p2.x, p2.y, p3.x, p3.y);
    }
}

// =====================================================================
// Phase B: persistent recurrence v4.
// 128 CTAs x 256 threads. CTA -> (layer = cta>>6, 8 h-rows).
// k-SPLIT occupancy fix: thread = (khalf = tid>>7, hrow = tid&7,
// b4 = ((tid&127)>>3)*4). Each khalf accumulates 256 of 512 k (its 4 of the
// 8 16KB TMA chunks) for BOTH gates -> 2 warps/SMSP hide LDS/TMA latency.
// Cross-half reduce via 4KB smem. hold carried in registers across steps.
// U pre-duplicated f32x2 (stride-514 ull, conflict-free). Single-counter
// per-layer grid barrier (red.release arrive, 1-load acquire poll).
// =====================================================================
constexpr int H_BYTES  = 512 * 64 * 4;              // 131072
constexpr int USTRIDE2 = 514;                       // ull stride
constexpr int U_BYTES  = 16 * USTRIDE2 * 8;         // 65792
constexpr int RED_OFF  = H_BYTES + U_BYTES;         // 196864
constexpr int RED_BYTES = 128 * 8 * 4;              // 4096
constexpr int EX_OFF_B = RED_OFF + RED_BYTES;       // 200960
constexpr int EX_BYTES = 8 * 68 * 4;                // 2176
constexpr int MB_OFF_B = EX_OFF_B + EX_BYTES;       // 203136
constexpr int SMEM_BYTES = MB_OFF_B + 64;           // 203200 (8 mbarriers)

__global__ void __launch_bounds__(256, 1) recur_kernel(float* __restrict__ out)
{
    extern __shared__ __align__(16) char smem[];
    float*              Hsm = reinterpret_cast<float*>(smem);
    unsigned long long* Usm = reinterpret_cast<unsigned long long*>(smem + H_BYTES);
    float*              Red = reinterpret_cast<float*>(smem + RED_OFF);
    float*              Ex  = reinterpret_cast<float*>(smem + EX_OFF_B);
    uint32_t            mb0 = smem_u32(smem + MB_OFF_B);   // 8 mbarriers, 8B apart

    int tid = threadIdx.x;
    int cta = blockIdx.x;
    int l   = cta >> 6;
    int h0r = (cta & 63) * 8;

    // cache Ueff slice, duplicated into f32x2 pairs. rows 0-7 = z, 8-15 = n.
    for (int i = tid; i < 16 * 512; i += 256) {
        int r = i >> 9, k = i & 511;
        int g = r >> 3, hh = r & 7;
        float v = g_Ueff[(size_t)((l * 2 + g) * 512 + h0r + hh) * kK + k];
        Usm[r * USTRIDE2 + k] = pk2(v, v);
    }
    if (tid == 0) {
#pragma unroll
        for (int c = 0; c < 8; c++) mbar_init(mb0 + c * 8, 1);
        asm volatile("fence.proxy.async.shared::cta;" ::: "memory");
    }
    __syncthreads();

    int khalf = tid >> 7;          // 0 or 1: which half of k
    int sub   = tid & 127;
    int hrow  = sub & 7;
    int b4    = (sub >> 3) * 4;

    const unsigned long long* Uz = Usm + hrow * USTRIDE2 + khalf * 256;
    const unsigned long long* Un = Usm + (8 + hrow) * USTRIDE2 + khalf * 256;
    float biasz = g_bias[l * 1024 + h0r + hrow];
    float biasn = g_bias[l * 1024 + 512 + h0r + hrow];
    const size_t hoff = (size_t)l * (kHS * kB);
    unsigned* bar = &g_barc[l * 32];
    int cbase = khalf * 4;          // chunks 0-3 or 4-7 (64 k-rows each)

    // register-carried previous-h for this thread's (hrow, b4)
    float4 hlast = *reinterpret_cast<const float4*>(
        &g_h[0][hoff + (size_t)(h0r + hrow) * kB + b4]);

    unsigned target = 64;

    for (int t = 0; t < kS; t++) {
        const float* hcur = g_h[t & 1] + hoff;
        float*       hnxt = g_h[(t & 1) ^ 1] + hoff;
        uint32_t     par  = (unsigned)t & 1u;

        // stage full h (128KB) via 8x16KB bulk copies (TMA, off-crossbar)
        if (tid == 0) {
#pragma unroll
            for (int c = 0; c < 8; c++) {
                mbar_expect_tx(mb0 + c * 8, 16384u);
                bulk_g2s(smem_u32(Hsm + c * 4096), hcur + c * 4096, 16384u, mb0 + c * 8);
            }
        }

        // prefetch Gx for both gates (khalf 0 finalizes; hidden behind chunk waits)
        float4 gz, gn;
        if (khalf == 0) {
            const float* gxp = &g_Gx[((size_t)t * kM + l * 1024 + h0r + hrow) * kB + b4];
            gz = *reinterpret_cast<const float4*>(gxp);
            gn = *reinterpret_cast<const float4*>(gxp + 512 * kB);
        }

        unsigned long long cz0 = 0ull, cz1 = 0ull, cn0 = 0ull, cn1 = 0ull;
#pragma unroll
        for (int c = 0; c < 4; c++) {
            int ch = cbase + c;
            mbar_wait(mb0 + ch * 8, par);
            const float* hp = Hsm + ch * 4096 + b4;
            const unsigned long long* uz = Uz + c * 64;
            const unsigned long long* un = Un + c * 64;
#pragma unroll
            for (int kk = 0; kk < 64; kk += 4) {
                ulonglong2 az01 = *reinterpret_cast<const ulonglong2*>(uz + kk);
                ulonglong2 az23 = *reinterpret_cast<const ulonglong2*>(uz + kk + 2);
                ulonglong2 an01 = *reinterpret_cast<const ulonglong2*>(un + kk);
                ulonglong2 an23 = *reinterpret_cast<const ulonglong2*>(un + kk + 2);
                ulonglong2 h0v = *reinterpret_cast<const ulonglong2*>(hp + (kk + 0) * 64);
                fma2(cz0, az01.x, h0v.x); fma2(cz1, az01.x, h0v.y);
                fma2(cn0, an01.x, h0v.x); fma2(cn1, an01.x, h0v.y);
                ulonglong2 h1v = *reinterpret_cast<const ulonglong2*>(hp + (kk + 1) * 64);
                fma2(cz0, az01.y, h1v.x); fma2(cz1, az01.y, h1v.y);
                fma2(cn0, an01.y, h1v.x); fma2(cn1, an01.y, h1v.y);
                ulonglong2 h2v = *reinterpret_cast<const ulonglong2*>(hp + (kk + 2) * 64);
                fma2(cz0, az23.x, h2v.x); fma2(cz1, az23.x, h2v.y);
                fma2(cn0, an23.x, h2v.x); fma2(cn1, an23.x, h2v.y);
                ulonglong2 h3v = *reinterpret_cast<const ulonglong2*>(hp + (kk + 3) * 64);
                fma2(cz0, az23.y, h3v.x); fma2(cz1, az23.y, h3v.y);
                fma2(cn0, an23.y, h3v.x); fma2(cn1, an23.y, h3v.y);
            }
        }

        // khalf 1 publishes its partials (z0..3, n0..3)
        if (khalf == 1) {
            float2 z01 = up2(cz0), z23 = up2(cz1);
            float2 n01 = up2(cn0), n23 = up2(cn1);
            float* rp = Red + sub * 8;
            *reinterpret_cast<float4*>(rp)     = make_float4(z01.x, z01.y, z23.x, z23.y);
            *reinterpret_cast<float4*>(rp + 4) = make_float4(n01.x, n01.y, n23.x, n23.y);
        }
        __syncthreads();

        // khalf 0: reduce, activations, combine (hold in registers), write h'
        if (khalf == 0) {
            const float* rp = Red + sub * 8;
            float4 zr = *reinterpret_cast<const float4*>(rp);
            float4 nr = *reinterpret_cast<const float4*>(rp + 4);
            float2 z01 = up2(cz0), z23 = up2(cz1);
            float2 n01 = up2(cn0), n23 = up2(cn1);
            float qz0 = (z01.x + zr.x) + gz.x + biasz;
            float qz1 = (z01.y + zr.y) + gz.y + biasz;
            float qz2 = (z23.x + zr.z) + gz.z + biasz;
            float qz3 = (z23.y + zr.w) + gz.w + biasz;
            float qn0 = (n01.x + nr.x) + gn.x + biasn;
            float qn1 = (n01.y + nr.y) + gn.y + biasn;
            float qn2 = (n23.x + nr.z) + gn.z + biasn;
            float qn3 = (n23.y + nr.w) + gn.w + biasn;
            float z0 = 1.f / (1.f + __expf(-qz0));
            float z1 = 1.f / (1.f + __expf(-qz1));
            float z2 = 1.f / (1.f + __expf(-qz2));
            float z3 = 1.f / (1.f + __expf(-qz3));
            float n0 = tanhf(qn0), n1 = tanhf(qn1), n2 = tanhf(qn2), n3 = tanhf(qn3);

            hlast.x = fmaf(z0, hlast.x - n0, n0);
            hlast.y = fmaf(z1, hlast.y - n1, n1);
            hlast.z = fmaf(z2, hlast.z - n2, n2);
            hlast.w = fmaf(z3, hlast.w - n3, n3);

            *reinterpret_cast<float4*>(&hnxt[(size_t)(h0r + hrow) * kB + b4]) = hlast;
            if (l == 1)
                *reinterpret_cast<float4*>(&Ex[hrow * 68 + b4]) = hlast;
        }
        __syncthreads();

        // last layer emits hidden_seq[b][t][h] (h-fastest, 32B segments)
        if (l == 1) {
#pragma unroll
            for (int it = 0; it < 2; it++) {
                int item = tid + it * 256;
                int b  = item >> 3;
                int hh = item & 7;
                out[((size_t)b * kS + t) * kHS + h0r + hh] = Ex[hh * 68 + b];
            }
        }

        // per-layer grid barrier: single-counter red.release arrive + 1-load poll
        if (tid == 0) {
            asm volatile("red.release.gpu.global.add.u32 [%0], %1;"
                         :: "l"(bar), "r"(1u) : "memory");
            unsigned v;
            do {
                asm volatile("ld.acquire.gpu.global.u32 %0, [%1];"
                             : "=r"(v) : "l"(bar) : "memory");
            } while (v < target);
        }
        __syncthreads();
        target += 64;
    }

    // final state (L,B,HS) from registers (khalf 0 holds the live h)
    if (khalf == 0) {
        float* stout = out + (size_t)kB * kS * kHS;
        stout[((size_t)(l * kB + b4 + 0)) * kHS + h0r + hrow] = hlast.x;
        stout[((size_t)(l * kB + b4 + 1)) * kHS + h0r + hrow] = hlast.y;
        stout[((size_t)(l * kB + b4 + 2)) * kHS + h0r + hrow] = hlast.z;
        stout[((size_t)(l * kB + b4 + 3)) * kHS + h0r + hrow] = hlast.w;
    }
}

// =====================================================================
extern "C" void kernel_launch(void* const* d_in, const int* in_sizes, int n_in,
                              void* d_out, int out_size)
{
    const float* x   = (const float*)d_in[0];
    const float* h0  = (const float*)d_in[1];
    const float* W1  = (const float*)d_in[2];
    const float* W2  = (const float*)d_in[3];
    const float* U1  = (const float*)d_in[4];
    const float* U2  = (const float*)d_in[5];
    const float* dW1 = (const float*)d_in[6];
    const float* dW2 = (const float*)d_in[7];
    const float* dU1 = (const float*)d_in[8];
    const float* dU2 = (const float*)d_in[9];
    const float* b1  = (const float*)d_in[10];
    const float* b2  = (const float*)d_in[11];
    float* out = (float*)d_out;

    cudaFuncSetAttribute(recur_kernel,
                         cudaFuncAttributeMaxDynamicSharedMemorySize, SMEM_BYTES);

    prep_kernel<<<512, 256>>>(h0, W1, W2, U1, U2, dW1, dW2, dU1, dU2, b1, b2);

    dim3 ggrid(kN / GBN, kM / GBM);   // (512, 16)
    gemm_kernel<<<ggrid, 256>>>(x);

    recur_kernel<<<128, 256, SMEM_BYTES>>>(out);
}

// round 17
// speedup vs baseline: 1.2167x; 1.2167x over previous
#include <cuda_runtime.h>
#include <cstdint>
#include <cstddef>

// Problem constants
constexpr int kL   = 2;
constexpr int kHS  = 512;
constexpr int kIN  = 512;
constexpr int kB   = 64;
constexpr int kS   = 1024;
constexpr int kM   = 2048;              // (l,g,h): m = (l*2+g)*512 + h   (g: 0=z, 1=n)
constexpr int kK   = 512;
constexpr int kN   = kS * kB;           // n = t*64 + b

// ---------------- device scratch (static allocation, allowed) ----------------
__device__ float    g_Weff[(size_t)kM * kK];          // 4 MB
__device__ float    g_Ueff[(size_t)kM * kK];          // 4 MB
__device__ float    g_bias[kM];
__device__ float    g_Gx[(size_t)kS * kM * kB];       // 512 MB: [t][bq][m][16b]
__device__ float    g_h[2][kL * 4 * kHS * 16];        // ping-pong, [l][bq][k][16b]
__device__ unsigned g_barc[8 * 32];                   // one counter per (l,bq), 128B apart

// ---------------- packed f32x2 helpers ----------------
__device__ __forceinline__ unsigned long long pk2(float x, float y) {
    unsigned long long r;
    asm("mov.b64 %0, {%1, %2};" : "=l"(r) : "f"(x), "f"(y));
    return r;
}
__device__ __forceinline__ void fma2(unsigned long long& c, unsigned long long a, unsigned long long b) {
    asm("fma.rn.f32x2 %0, %1, %2, %0;" : "+l"(c) : "l"(a), "l"(b));
}
__device__ __forceinline__ float2 up2(unsigned long long v) {
    float lo, hi;
    asm("mov.b64 {%0, %1}, %2;" : "=f"(lo), "=f"(hi) : "l"(v));
    return make_float2(lo, hi);
}

__device__ __forceinline__ uint32_t smem_u32(const void* p) {
    uint32_t a;
    asm("{ .reg .u64 t; cvta.to.shared.u64 t, %1; cvt.u32.u64 %0, t; }" : "=r"(a) : "l"(p));
    return a;
}
__device__ __forceinline__ void mbar_init(uint32_t addr, uint32_t cnt) {
    asm volatile("mbarrier.init.shared.b64 [%0], %1;" :: "r"(addr), "r"(cnt) : "memory");
}
__device__ __forceinline__ void mbar_expect_tx(uint32_t addr, uint32_t bytes) {
    asm volatile("mbarrier.arrive.expect_tx.shared.b64 _, [%0], %1;" :: "r"(addr), "r"(bytes) : "memory");
}
__device__ __forceinline__ void mbar_wait(uint32_t addr, uint32_t phase) {
    asm volatile(
        "{\n\t.reg .pred P;\n\t"
        "W%=:\n\t"
        "mbarrier.try_wait.parity.acquire.cta.shared::cta.b64 P, [%0], %1, 0x989680;\n\t"
        "@!P bra W%=;\n\t}"
        :: "r"(addr), "r"(phase) : "memory");
}
__device__ __forceinline__ void bulk_g2s(uint32_t dst, const void* src, uint32_t bytes, uint32_t mbar) {
    asm volatile(
        "cp.async.bulk.shared::cta.global.mbarrier::complete_tx::bytes [%0], [%1], %2, [%3];"
        :: "r"(dst), "l"(src), "r"(bytes), "r"(mbar) : "memory");
}

// =====================================================================
// Prep: fold rank-1 gate scalars into effective weights, init h, bias, barriers
// =====================================================================
__global__ void prep_kernel(const float* __restrict__ h0,
                            const float* __restrict__ W1, const float* __restrict__ W2,
                            const float* __restrict__ U1, const float* __restrict__ U2,
                            const float* __restrict__ dW1, const float* __restrict__ dW2,
                            const float* __restrict__ dU1, const float* __restrict__ dU2,
                            const float* __restrict__ b1, const float* __restrict__ b2)
{
    int gsz = gridDim.x * blockDim.x;
    int gid = blockIdx.x * blockDim.x + threadIdx.x;

    for (int i = gid; i < kM * kK; i += gsz) {
        int m = i >> 9, k = i & 511;
        int l = m >> 10, g = (m >> 9) & 1, h = m & 511;
        // gate index in the 3-gate source: z=1, n=2 (r unused)
        float w1  = W1[l * 3 + g + 1],  dw1 = dW1[l * 3 + g + 1];
        float u1  = U1[l * 3 + g + 1],  du1 = dU1[l * 3 + g + 1];
        int wi = (l * kHS + h) * kIN + k;
        g_Weff[i] = w1 * W2[wi] + dw1 * dW2[wi];
        g_Ueff[i] = u1 * U2[wi] + du1 * dU2[wi];
        if (k == 0) {
            int bi = l * 3 * kHS + (g + 1) * kHS + h;
            g_bias[m] = b1[bi] + b2[bi];
        }
    }
    // h buffer [l][bq][k(512)][16b] <- h0 (L,B,HS)
    for (int j = gid; j < kL * 4 * kHS * 16; j += gsz) {
        int l  = j >> 15;
        int bq = (j >> 13) & 3;
        int hk = (j >> 4) & 511;
        int bb = j & 15;
        g_h[0][j] = h0[(l * kB + bq * 16 + bb) * kHS + hk];
    }
    if (gid < 8 * 32) g_barc[gid] = 0u;
}

// =====================================================================
// Phase A: Gx[t][bq][m][16b] = sum_k Weff[m][k] * x[b][t][k]
// 128x128x16 tiles, 256 threads, 8x8 per thread, f32x2 packed FMA
// =====================================================================
constexpr int GBM = 128, GBN = 128, GBK = 16, GPAD = 4;

__global__ void __launch_bounds__(256, 2) gemm_kernel(const float* __restrict__ x)
{
    __shared__ __align__(16) float As[GBK][GBM + GPAD];
    __shared__ __align__(16) float Bs[GBK][GBN + GPAD];

    int tid = threadIdx.x;
    int m0 = blockIdx.y * GBM;     // grid.y = 16
    int n0 = blockIdx.x * GBN;     // grid.x = 512
    int tm = tid >> 4, tn = tid & 15;

    unsigned long long c[8][4];
#pragma unroll
    for (int i = 0; i < 8; i++)
#pragma unroll
        for (int j = 0; j < 4; j++) c[i][j] = 0ull;

    for (int kt = 0; kt < kK; kt += GBK) {
#pragma unroll
        for (int it = 0; it < 2; it++) {
            int fid = tid + it * 256;
            int row = fid >> 2;
            int k4  = (fid & 3) * 4;
            float4 av = *reinterpret_cast<const float4*>(
                &g_Weff[(size_t)(m0 + row) * kK + kt + k4]);
            As[k4 + 0][row] = av.x; As[k4 + 1][row] = av.y;
            As[k4 + 2][row] = av.z; As[k4 + 3][row] = av.w;
            int n = n0 + row;
            int b = n & 63, t = n >> 6;
            float4 bv = *reinterpret_cast<const float4*>(
                &x[((size_t)b * kS + t) * kIN + kt + k4]);
            Bs[k4 + 0][row] = bv.x; Bs[k4 + 1][row] = bv.y;
            Bs[k4 + 2][row] = bv.z; Bs[k4 + 3][row] = bv.w;
        }
        __syncthreads();
#pragma unroll
        for (int kk = 0; kk < GBK; kk++) {
            float4 alo = *reinterpret_cast<const float4*>(&As[kk][tm * 8]);
            float4 ahi = *reinterpret_cast<const float4*>(&As[kk][tm * 8 + 4]);
            float a[8] = {alo.x, alo.y, alo.z, alo.w, ahi.x, ahi.y, ahi.z, ahi.w};
            ulonglong2 b01 = *reinterpret_cast<const ulonglong2*>(&Bs[kk][tn * 8]);
            ulonglong2 b23 = *reinterpret_cast<const ulonglong2*>(&Bs[kk][tn * 8 + 4]);
            unsigned long long bq[4] = {b01.x, b01.y, b23.x, b23.y};
#pragma unroll
            for (int i = 0; i < 8; i++) {
                unsigned long long ad = pk2(a[i], a[i]);
#pragma unroll
                for (int j = 0; j < 4; j++) fma2(c[i][j], ad, bq[j]);
            }
        }
        __syncthreads();
    }

    // store: thread's 8 n-values are 8 consecutive b within one t and one bq
    int nbase = n0 + tn * 8;
    int b0 = nbase & 63;
    int tt = nbase >> 6;
    int bqi = b0 >> 4;
    int bb  = b0 & 15;
#pragma unroll
    for (int i = 0; i < 8; i++) {
        int m = m0 + tm * 8 + i;
        float* dst = &g_Gx[(((size_t)tt * 4 + bqi) * kM + m) * 16 + bb];
        float2 p0 = up2(c[i][0]), p1 = up2(c[i][1]);
        float2 p2 = up2(c[i][2]), p3 = up2(c[i][3]);
        *reinterpret_cast<float4*>(dst)     = make_float4(p0.x, p0.y, p1.x, p1.y);
        *reinterpret_cast<float4*>(dst + 4) = make_float4(p2.x, p2.y, p3.x, p3.y);
    }
}

// =====================================================================
// Phase B: persistent recurrence v6 — batch-quarter partition (FIXED coverage).
// 128 CTAs x 512 threads. CTA = (layer = cta>>6, bq = (cta>>4)&3, rg = cta&15).
// CTA owns 32 h-rows x 16 b  (16 rg x 32 rows = 512 = HS ✓).
// h exchange per (layer,bq) group: 16 CTAs, 32 KB staged by 4x8KB TMA.
// k-loop role: thread = (gr = tid&63 gate-row (0-31 z, 32-63 n),
//                        kc = tid>>6 k-chunk of 64). U[64] in REGISTERS;
// h rows read via warp-broadcast LDS.128 (lanes share the address).
// reduce via padded smem; combine role: thread = (cb = tid&15, chr = tid>>4).
// Per-group 16-arrival barrier (red.release + 1-load acquire poll).
// =====================================================================
constexpr int H_FLOATS   = kHS * 16;                 // 8192 floats = 32 KB
constexpr int RED_STRIDE = 18;                       // ull stride per entry (16B aligned)
constexpr int RED_OFF_B  = H_FLOATS * 4;             // 32768
constexpr int RED_BYTES  = 512 * RED_STRIDE * 8;     // 73728
constexpr int MB_OFF_B   = RED_OFF_B + RED_BYTES;    // 106496
constexpr int SMEM_BYTES = MB_OFF_B + 32;            // 106528 (4 mbarriers)

__global__ void __launch_bounds__(512, 1) recur_kernel(float* __restrict__ out)
{
    extern __shared__ __align__(16) char smem[];
    float*              Hsm  = reinterpret_cast<float*>(smem);
    unsigned long long* Red  = reinterpret_cast<unsigned long long*>(smem + RED_OFF_B);
    const float*        RedF = reinterpret_cast<const float*>(smem + RED_OFF_B);
    uint32_t            mb0  = smem_u32(smem + MB_OFF_B);   // 4 mbarriers, 8B apart

    int tid = threadIdx.x;
    int cta = blockIdx.x;
    int l   = cta >> 6;
    int bq  = (cta >> 4) & 3;
    int rg  = cta & 15;

    // ----- k-loop role -----
    int gr = tid & 63;           // 0-31 z-rows, 32-63 n-rows (within this row-group)
    int kc = tid >> 6;           // k-chunk: 64 k each (0..7)

    // U slice into registers: row m, k in [kc*64, kc*64+64)
    float u[64];
    {
        int m = l * 1024 + (gr >> 5) * 512 + rg * 32 + (gr & 31);
        const float4* up = reinterpret_cast<const float4*>(
            &g_Ueff[(size_t)m * kK + kc * 64]);
#pragma unroll
        for (int i = 0; i < 16; i++) {
            float4 v = up[i];
            u[i * 4 + 0] = v.x; u[i * 4 + 1] = v.y;
            u[i * 4 + 2] = v.z; u[i * 4 + 3] = v.w;
        }
    }

    // ----- combine role -----
    int cb  = tid & 15;          // batch within quarter
    int chr = tid >> 4;          // h-row within group (0-31)
    int mz  = l * 1024 + rg * 32 + chr;
    float biasz = g_bias[mz];
    float biasn = g_bias[mz + 512];

    if (tid == 0) {
#pragma unroll
        for (int c = 0; c < 4; c++) mbar_init(mb0 + c * 8, 1);
        asm volatile("fence.proxy.async.shared::cta;" ::: "memory");
    }
    __syncthreads();

    const size_t hoff = (size_t)(l * 4 + bq) * H_FLOATS;
    unsigned* bar = &g_barc[(l * 4 + bq) * 32];
    uint32_t mymb = mb0 + (kc >> 1) * 8;

    float hnew = 0.f;
    unsigned target = 16;

    for (int t = 0; t < kS; t++) {
        const float* hcur = g_h[t & 1] + hoff;
        float*       hnxt = g_h[(t & 1) ^ 1] + hoff;
        uint32_t     par  = (unsigned)t & 1u;

        // stage group h (32 KB) via 4x8KB bulk copies
        if (tid == 0) {
#pragma unroll
            for (int c = 0; c < 4; c++) {
                mbar_expect_tx(mb0 + c * 8, 8192u);
                bulk_g2s(smem_u32(Hsm + c * 2048), hcur + c * 2048, 8192u, mb0 + c * 8);
            }
        }

        // prefetch Gx with combine-role mapping (coalesced 64B rows)
        const float* gxp = &g_Gx[(((size_t)t * 4 + bq) * kM + mz) * 16 + cb];
        float gz = gxp[0];
        float gn = gxp[512 * 16];

        // k-loop: this thread accumulates (gr-row) x (16 b) over its 64 k
        unsigned long long a0 = 0ull, a1 = 0ull, a2 = 0ull, a3 = 0ull;
        unsigned long long a4 = 0ull, a5 = 0ull, a6 = 0ull, a7 = 0ull;
        mbar_wait(mymb, par);
        {
            const ulonglong2* hp = reinterpret_cast<const ulonglong2*>(Hsm + kc * 64 * 16);
#pragma unroll
            for (int k = 0; k < 64; k++) {
                unsigned long long ud = pk2(u[k], u[k]);
                ulonglong2 h0 = hp[k * 4 + 0];
                ulonglong2 h1 = hp[k * 4 + 1];
                ulonglong2 h2 = hp[k * 4 + 2];
                ulonglong2 h3 = hp[k * 4 + 3];
                fma2(a0, ud, h0.x); fma2(a1, ud, h0.y);
                fma2(a2, ud, h1.x); fma2(a3, ud, h1.y);
                fma2(a4, ud, h2.x); fma2(a5, ud, h2.y);
                fma2(a6, ud, h3.x); fma2(a7, ud, h3.y);
            }
        }
        // publish partials (16 floats) at entry (kc*64 + gr)
        {
            ulonglong2* rp = reinterpret_cast<ulonglong2*>(Red + (kc * 64 + gr) * RED_STRIDE);
            rp[0] = make_ulonglong2(a0, a1);
            rp[1] = make_ulonglong2(a2, a3);
            rp[2] = make_ulonglong2(a4, a5);
            rp[3] = make_ulonglong2(a6, a7);
        }
        __syncthreads();

        // combine: sum 8 k-chunks for (chr, cb), both gates
        {
            float zs = 0.f, ns = 0.f;
#pragma unroll
            for (int c8 = 0; c8 < 8; c8++) {
                zs += RedF[(c8 * 64 + chr) * (RED_STRIDE * 2) + cb];
                ns += RedF[(c8 * 64 + 32 + chr) * (RED_STRIDE * 2) + cb];
            }
            float qz = zs + gz + biasz;
            float qn = ns + gn + biasn;
            float zv = 1.f / (1.f + __expf(-qz));
            float nv = tanhf(qn);
            float hold = Hsm[(rg * 32 + chr) * 16 + cb];
            hnew = fmaf(zv, hold - nv, nv);          // (1-z)*n + z*h
            hnxt[(rg * 32 + chr) * 16 + cb] = hnew;
            if (l == 1)
                out[((size_t)(bq * 16 + cb) * kS + t) * kHS + rg * 32 + chr] = hnew;
        }
        __syncthreads();

        // per-(layer,bq) group barrier: 16 arrivals
        if (tid == 0) {
            asm volatile("red.release.gpu.global.add.u32 [%0], %1;"
                         :: "l"(bar), "r"(1u) : "memory");
            unsigned v;
            do {
                asm volatile("ld.acquire.gpu.global.u32 %0, [%1];"
                             : "=r"(v) : "l"(bar) : "memory");
            } while (v < target);
        }
        __syncthreads();
        target += 16;
    }

    // final state (L,B,HS) from register
    float* stout = out + (size_t)kB * kS * kHS;
    stout[((size_t)(l * kB + bq * 16 + cb)) * kHS + rg * 32 + chr] = hnew;
}

// =====================================================================
extern "C" void kernel_launch(void* const* d_in, const int* in_sizes, int n_in,
                              void* d_out, int out_size)
{
    const float* x   = (const float*)d_in[0];
    const float* h0  = (const float*)d_in[1];
    const float* W1  = (const float*)d_in[2];
    const float* W2  = (const float*)d_in[3];
    const float* U1  = (const float*)d_in[4];
    const float* U2  = (const float*)d_in[5];
    const float* dW1 = (const float*)d_in[6];
    const float* dW2 = (const float*)d_in[7];
    const float* dU1 = (const float*)d_in[8];
    const float* dU2 = (const float*)d_in[9];
    const float* b1  = (const float*)d_in[10];
    const float* b2  = (const float*)d_in[11];
    float* out = (float*)d_out;

    cudaFuncSetAttribute(recur_kernel,
                         cudaFuncAttributeMaxDynamicSharedMemorySize, SMEM_BYTES);

    prep_kernel<<<512, 256>>>(h0, W1, W2, U1, U2, dW1, dW2, dU1, dU2, b1, b2);

    dim3 ggrid(kN / GBN, kM / GBM);   // (512, 16)
    gemm_kernel<<<ggrid, 256>>>(x);

    recur_kernel<<<128, 512, SMEM_BYTES>>>(out);
}